// round 8
// baseline (speedup 1.0000x reference)
#include <cuda_runtime.h>
#include <cuda_bf16.h>
#include <math.h>

// ===========================================================================
// MS-SSIM 16x3x512x512 fp32, 5 levels.
// ssim_level_kernel:
//   - SMEM tile: interleaved float2 (a,b)
//   - per input row: stage float4 (a, b, a^2+b^2, a*b) into a ping-pong SMEM
//     row buffer (one __syncthreads per row), so per-pixel products are
//     computed ONCE instead of once per tap-reader
//   - horizontal: 11x (LDS.128 + fma2 + 2x FFMA-imm)   [4 fma-cyc/tap]
//   - rings: packed (mu1,mu2), scalar ss=a2+b2 conv, scalar xy conv
//   - vertical: 11x (fma2 + 2x FFMA-imm)
//   - per-pixel SSIM/CS, block reduce, atomicAdd into double accumulators
// pool2_kernel: fused 2x avg-pool of both images, float4 loads.
// ===========================================================================

#define OC   128          // output columns per block (== threads)
#define ORR  26           // output rows per block
#define IR   (ORR + 10)   // 36 input rows
#define ICW  (OC + 10)    // 138 input cols
#define BUFW 140          // row-buffer width (float4-aligned padding)

// Gaussian taps, sigma=1.5, ws=11
#define G0 0.00102838f
#define G1 0.00759876f
#define G2 0.03600077f
#define G3 0.10936069f
#define G4 0.21300553f
#define G5 0.26601172f

#define C1V 1.0e-4f
#define C2V 9.0e-4f

// Scratch for pooled pyramids
#define S1 (48u * 256u * 256u)
#define S2 (48u * 128u * 128u)
#define S3 (48u * 64u  * 64u)
#define S4 (48u * 32u  * 32u)
#define O1 0u
#define O2 (S1)
#define O3 (S1 + S2)
#define O4 (S1 + S2 + S3)
#define TOT (S1 + S2 + S3 + S4)

__device__ float g_p1[TOT];
__device__ float g_p2[TOT];
__device__ double g_acc[10];

// ---- f32x2 packed helpers -------------------------------------------------
typedef unsigned long long ull;
__device__ __forceinline__ ull pk2(float lo, float hi) {
    ull r;
    asm("mov.b64 %0, {%1, %2};" : "=l"(r) : "f"(lo), "f"(hi));
    return r;
}
__device__ __forceinline__ void upk2(ull v, float& lo, float& hi) {
    asm("mov.b64 {%0, %1}, %2;" : "=f"(lo), "=f"(hi) : "l"(v));
}
__device__ __forceinline__ ull fma2(ull a, ull b, ull c) {
    ull d;
    asm("fma.rn.f32x2 %0, %1, %2, %3;" : "=l"(d) : "l"(a), "l"(b), "l"(c));
    return d;
}

__global__ void zero_acc_kernel() {
    if (threadIdx.x < 10) g_acc[threadIdx.x] = 0.0;
}

__global__ void __launch_bounds__(OC, 5)
ssim_level_kernel(const float* __restrict__ A, const float* __restrict__ B,
                  int H, int level) {
    __shared__ float2 sAB[IR * ICW];
    __shared__ float4 sRow[2][BUFW];   // ping-pong staged row

    const int tid = threadIdx.x;
    const int rowBase = blockIdx.y * ORR;
    const int colBase = blockIdx.x * OC;
    const int W = H;
    const size_t zoff = (size_t)blockIdx.z * H * W;
    const float* __restrict__ Ap = A + zoff;
    const float* __restrict__ Bp = B + zoff;

    // ---- load interleaved tile (zero-clamped halo; masked outputs) ----
    for (int i = tid; i < IR * ICW; i += OC) {
        int r = i / ICW;
        int c = i - r * ICW;
        int gr = rowBase + r, gc = colBase + c;
        float a = 0.f, b = 0.f;
        if (gr < H && gc < W) {
            size_t o = (size_t)gr * W + gc;
            a = __ldg(Ap + o);
            b = __ldg(Bp + o);
        }
        sAB[i] = make_float2(a, b);
    }
    __syncthreads();

    const int oc = colBase + tid;
    const bool col_ok = oc < (W - 10);

    // 6 distinct packed taps (symmetry); scalar taps stay literal immediates
    ull Gp[6];
    Gp[0] = pk2(G0, G0); Gp[1] = pk2(G1, G1); Gp[2] = pk2(G2, G2);
    Gp[3] = pk2(G3, G3); Gp[4] = pk2(G4, G4); Gp[5] = pk2(G5, G5);

    const float Gf[11] = {G0, G1, G2, G3, G4, G5, G4, G3, G2, G1, G0};

    // rings: packed (mu1,mu2), scalar a^2+b^2, scalar a*b
    ull   rMu[11];
    float rSS[11];
    float rXY[11];
    float accS = 0.f, accC = 0.f;

    #pragma unroll
    for (int r = 0; r < IR; r++) {
        // ---- stage row r: (a, b, a^2+b^2, a*b), computed once per pixel ----
        {
            float2 v = sAB[r * ICW + tid];
            sRow[r & 1][tid] =
                make_float4(v.x, v.y, fmaf(v.x, v.x, v.y * v.y), v.x * v.y);
            if (tid < ICW - OC) {
                float2 w = sAB[r * ICW + OC + tid];
                sRow[r & 1][OC + tid] =
                    make_float4(w.x, w.y, fmaf(w.x, w.x, w.y * w.y), w.x * w.y);
            }
        }
        __syncthreads();

        // ---- horizontal pass: 11x (LDS.128 + fma2 + 2x FFMA-imm) ----
        ull s12 = 0ull;
        float sss = 0.f, sxy = 0.f;
        const float4* __restrict__ rb = &sRow[r & 1][tid];
        #pragma unroll
        for (int k = 0; k < 11; k++) {
            float4 q = rb[k];                         // LDS.128
            ull vp = pk2(q.x, q.y);
            s12 = fma2(vp, Gp[k < 6 ? k : 10 - k], s12);
            sss = fmaf(q.z, Gf[k], sss);              // FFMA-imm
            sxy = fmaf(q.w, Gf[k], sxy);              // FFMA-imm
        }
        const int slot = r % 11;                      // compile-time
        rMu[slot] = s12;
        rSS[slot] = sss;
        rXY[slot] = sxy;

        // ---- vertical pass ----
        if (r >= 10) {
            ull m12 = 0ull;
            float mss = 0.f, mxy = 0.f;
            #pragma unroll
            for (int j = 0; j < 11; j++) {
                const int sl = (r - 10 + j) % 11;     // compile-time
                m12 = fma2(rMu[sl], Gp[j < 6 ? j : 10 - j], m12);
                mss = fmaf(rSS[sl], Gf[j], mss);      // FFMA-imm
                mxy = fmaf(rXY[sl], Gf[j], mxy);      // FFMA-imm
            }
            int gr = rowBase + r;
            if (col_ok && gr < H) {
                float m1, m2;
                upk2(m12, m1, m2);
                float t = m1 * m1;
                float mu11p22 = fmaf(m2, m2, t);      // m1^2 + m2^2
                float mu12 = m1 * m2;
                float v1 = 2.f * (mxy - mu12) + C2V;
                float v2 = (mss - mu11p22) + C2V;
                float cs = __fdividef(v1, v2);
                float ssim = cs * __fdividef(2.f * mu12 + C1V, mu11p22 + C1V);
                accS += ssim;
                accC += cs;
            }
        }
    }

    // ---- block reduction ----
    #pragma unroll
    for (int off = 16; off > 0; off >>= 1) {
        accS += __shfl_down_sync(0xFFFFFFFFu, accS, off);
        accC += __shfl_down_sync(0xFFFFFFFFu, accC, off);
    }
    __shared__ float wS[OC / 32], wC[OC / 32];
    const int warp = tid >> 5, lane = tid & 31;
    if (lane == 0) { wS[warp] = accS; wC[warp] = accC; }
    __syncthreads();
    if (tid == 0) {
        float bs = 0.f, bc = 0.f;
        #pragma unroll
        for (int wi = 0; wi < OC / 32; wi++) { bs += wS[wi]; bc += wC[wi]; }
        atomicAdd(&g_acc[2 * level],     (double)bs);
        atomicAdd(&g_acc[2 * level + 1], (double)bc);
    }
}

// Fused 2x avg-pool of both images; float4 loads, float2 stores; shift math.
__global__ void pool2_kernel(const float* __restrict__ s1, const float* __restrict__ s2,
                             float* __restrict__ d1, float* __restrict__ d2,
                             int logWs, int total2) {
    int idx = blockIdx.x * blockDim.x + threadIdx.x;
    if (idx >= total2) return;
    const int whalf_bits = logWs - 2;
    const int ho_bits    = logWs - 1;
    int xp = idx & ((1 << whalf_bits) - 1);
    int t  = idx >> whalf_bits;
    int y  = t & ((1 << ho_bits) - 1);
    int z  = t >> ho_bits;
    size_t off = (((size_t)((z << logWs) + (y << 1))) << logWs) + ((size_t)xp << 2);
    int Ws = 1 << logWs;

    float4 a0 = *(const float4*)(s1 + off);
    float4 a1 = *(const float4*)(s1 + off + Ws);
    float4 b0 = *(const float4*)(s2 + off);
    float4 b1 = *(const float4*)(s2 + off + Ws);

    float2 oa = make_float2(0.25f * (a0.x + a0.y + a1.x + a1.y),
                            0.25f * (a0.z + a0.w + a1.z + a1.w));
    float2 ob = make_float2(0.25f * (b0.x + b0.y + b1.x + b1.y),
                            0.25f * (b0.z + b0.w + b1.z + b1.w));
    ((float2*)d1)[idx] = oa;
    ((float2*)d2)[idx] = ob;
}

__global__ void final_kernel(float* __restrict__ out) {
    const double Hl[5] = {502.0, 246.0, 118.0, 54.0, 22.0};
    const double Wt[5] = {0.0448, 0.2856, 0.3001, 0.2363, 0.1333};
    double prod = 1.0;
    double ms4 = 0.0;
    for (int l = 0; l < 5; l++) {
        double cnt = 48.0 * Hl[l] * Hl[l];
        double ms = (g_acc[2 * l]     / cnt + 1.0) * 0.5;
        double mc = (g_acc[2 * l + 1] / cnt + 1.0) * 0.5;
        if (l < 4) prod *= pow(mc, Wt[l]);
        else       ms4 = pow(ms, Wt[4]);
    }
    prod *= ms4 * ms4 * ms4 * ms4;   // pow2[-1] enters all 4 product terms
    out[0] = (float)prod;
}

static inline void launch_level(const float* a, const float* b, int H, int level) {
    int outw = H - 10;
    dim3 grid((outw + OC - 1) / OC, (outw + ORR - 1) / ORR, 48);
    ssim_level_kernel<<<grid, OC>>>(a, b, H, level);
}

static inline void launch_pool(const float* s1, const float* s2,
                               float* d1, float* d2, int logWs) {
    int Ws = 1 << logWs;
    int total2 = 48 * (Ws >> 1) * (Ws >> 2);
    pool2_kernel<<<(total2 + 255) / 256, 256>>>(s1, s2, d1, d2, logWs, total2);
}

extern "C" void kernel_launch(void* const* d_in, const int* in_sizes, int n_in,
                              void* d_out, int out_size) {
    const float* img1 = (const float*)d_in[0];
    const float* img2 = (const float*)d_in[1];
    float* out = (float*)d_out;

    float* p1; float* p2;
    cudaGetSymbolAddress((void**)&p1, g_p1);
    cudaGetSymbolAddress((void**)&p2, g_p2);

    zero_acc_kernel<<<1, 32>>>();

    launch_level(img1, img2, 512, 0);
    launch_pool(img1, img2, p1 + O1, p2 + O1, 9);

    launch_level(p1 + O1, p2 + O1, 256, 1);
    launch_pool(p1 + O1, p2 + O1, p1 + O2, p2 + O2, 8);

    launch_level(p1 + O2, p2 + O2, 128, 2);
    launch_pool(p1 + O2, p2 + O2, p1 + O3, p2 + O3, 7);

    launch_level(p1 + O3, p2 + O3, 64, 3);
    launch_pool(p1 + O3, p2 + O3, p1 + O4, p2 + O4, 6);

    launch_level(p1 + O4, p2 + O4, 32, 4);

    final_kernel<<<1, 1>>>(out);
}

// round 9
// speedup vs baseline: 1.2958x; 1.2958x over previous
#include <cuda_runtime.h>
#include <cuda_bf16.h>
#include <math.h>

// ===========================================================================
// MS-SSIM 16x3x512x512 fp32, 5 levels.
// ssim_level_kernel (sum/difference transform):
//   SMEM tile holds packed (u,w) = (a+b, a-b) per pixel.
//   conv(a)        = (conv(u)+conv(w))/2      (packed lane recovery)
//   conv(a^2+b^2)  = (conv(u^2)+conv(w^2))/2
//   conv(a*b)      = (conv(u^2)-conv(w^2))/4
//   horizontal: 11x (LDS.64 + mul2 + 2x fma2)   [6 fma-cyc/tap, 2 phases]
//   vertical:   11x (2x fma2) over two packed register rings
//   epilogue: SSIM/CS from cu,cw,cU2,cW2; block reduce; atomicAdd doubles.
// pool2_kernel: fused 2x avg-pool of both images, float4 loads.
// ===========================================================================

#define OC  128           // output columns per block (== threads)
#define ORR 30            // output rows per block
#define IR  (ORR + 10)    // 40 input rows
#define ICW (OC + 10)     // 138 input cols

// Gaussian taps, sigma=1.5, ws=11
#define G0 0.00102838f
#define G1 0.00759876f
#define G2 0.03600077f
#define G3 0.10936069f
#define G4 0.21300553f
#define G5 0.26601172f

#define C1V 1.0e-4f
#define C2V 9.0e-4f

// Scratch for pooled pyramids
#define S1 (48u * 256u * 256u)
#define S2 (48u * 128u * 128u)
#define S3 (48u * 64u  * 64u)
#define S4 (48u * 32u  * 32u)
#define O1 0u
#define O2 (S1)
#define O3 (S1 + S2)
#define O4 (S1 + S2 + S3)
#define TOT (S1 + S2 + S3 + S4)

__device__ float g_p1[TOT];
__device__ float g_p2[TOT];
__device__ double g_acc[10];

// ---- f32x2 packed helpers -------------------------------------------------
typedef unsigned long long ull;
__device__ __forceinline__ ull pk2(float lo, float hi) {
    ull r;
    asm("mov.b64 %0, {%1, %2};" : "=l"(r) : "f"(lo), "f"(hi));
    return r;
}
__device__ __forceinline__ void upk2(ull v, float& lo, float& hi) {
    asm("mov.b64 {%0, %1}, %2;" : "=f"(lo), "=f"(hi) : "l"(v));
}
__device__ __forceinline__ ull fma2(ull a, ull b, ull c) {
    ull d;
    asm("fma.rn.f32x2 %0, %1, %2, %3;" : "=l"(d) : "l"(a), "l"(b), "l"(c));
    return d;
}
__device__ __forceinline__ ull mul2(ull a, ull b) {
    ull d;
    asm("mul.rn.f32x2 %0, %1, %2;" : "=l"(d) : "l"(a), "l"(b));
    return d;
}

__global__ void zero_acc_kernel() {
    if (threadIdx.x < 10) g_acc[threadIdx.x] = 0.0;
}

__global__ void __launch_bounds__(OC, 5)
ssim_level_kernel(const float* __restrict__ A, const float* __restrict__ B,
                  int H, int level) {
    __shared__ float2 sUW[IR * ICW];   // packed (a+b, a-b)

    const int tid = threadIdx.x;
    const int rowBase = blockIdx.y * ORR;
    const int colBase = blockIdx.x * OC;
    const int W = H;
    const size_t zoff = (size_t)blockIdx.z * H * W;
    const float* __restrict__ Ap = A + zoff;
    const float* __restrict__ Bp = B + zoff;

    // ---- load tile as (u,w) (zero-clamped halo; masked outputs) ----
    for (int i = tid; i < IR * ICW; i += OC) {
        int r = i / ICW;
        int c = i - r * ICW;
        int gr = rowBase + r, gc = colBase + c;
        float u = 0.f, w = 0.f;
        if (gr < H && gc < W) {
            size_t o = (size_t)gr * W + gc;
            float a = __ldg(Ap + o);
            float b = __ldg(Bp + o);
            u = a + b;
            w = a - b;
        }
        sUW[i] = make_float2(u, w);
    }
    __syncthreads();

    const int oc = colBase + tid;
    const bool col_ok = oc < (W - 10);

    // 6 distinct packed taps (symmetry)
    ull Gp[6];
    Gp[0] = pk2(G0, G0); Gp[1] = pk2(G1, G1); Gp[2] = pk2(G2, G2);
    Gp[3] = pk2(G3, G3); Gp[4] = pk2(G4, G4); Gp[5] = pk2(G5, G5);

    // two packed register rings: conv(u,w) and conv(u^2,w^2)
    ull rUW[11], rSQ[11];
    float accS = 0.f, accC = 0.f;

    #pragma unroll
    for (int r = 0; r < IR; r++) {
        // ---- horizontal pass: 11x (LDS.64 + mul2 + 2x fma2) ----
        ull sUWa = 0ull, sSQa = 0ull;
        const ull* __restrict__ rowp =
            reinterpret_cast<const ull*>(&sUW[r * ICW]) + tid;
        #pragma unroll
        for (int k = 0; k < 11; k++) {
            ull vp = rowp[k];                         // LDS.64 (u,w)
            ull g  = Gp[k < 6 ? k : 10 - k];
            sUWa = fma2(vp, g, sUWa);
            sSQa = fma2(mul2(vp, vp), g, sSQa);
        }
        const int slot = r % 11;                      // compile-time
        rUW[slot] = sUWa;
        rSQ[slot] = sSQa;

        // ---- vertical pass: 11x (2x fma2) ----
        if (r >= 10) {
            ull mUW = 0ull, mSQ = 0ull;
            #pragma unroll
            for (int j = 0; j < 11; j++) {
                const int sl = (r - 10 + j) % 11;     // compile-time
                ull g = Gp[j < 6 ? j : 10 - j];
                mUW = fma2(rUW[sl], g, mUW);
                mSQ = fma2(rSQ[sl], g, mSQ);
            }
            int gr = rowBase + r;
            if (col_ok && gr < H) {
                // recover SSIM terms from (cu,cw,cU2,cW2)
                float cU2, cW2, p, q;
                upk2(mSQ, cU2, cW2);
                ull pq = mul2(mUW, mUW);              // (cu^2, cw^2)
                upk2(pq, p, q);
                // 2*mu12 + C1 = (p-q)/2 + C1 ; mu11+mu22 + C1 = (p+q)/2 + C1
                // v1 = ((cU2-cW2) - (p-q))/2 + C2
                // v2 = ((cU2+cW2) - (p+q))/2 + C2
                float n1 = 0.5f * (p - q) + C1V;
                float d1 = 0.5f * (p + q) + C1V;
                float v1 = 0.5f * ((cU2 - cW2) - (p - q)) + C2V;
                float v2 = 0.5f * ((cU2 + cW2) - (p + q)) + C2V;
                float cs = __fdividef(v1, v2);
                float ssim = cs * __fdividef(n1, d1);
                accS += ssim;
                accC += cs;
            }
        }
    }

    // ---- block reduction ----
    #pragma unroll
    for (int off = 16; off > 0; off >>= 1) {
        accS += __shfl_down_sync(0xFFFFFFFFu, accS, off);
        accC += __shfl_down_sync(0xFFFFFFFFu, accC, off);
    }
    __shared__ float wS[OC / 32], wC[OC / 32];
    const int warp = tid >> 5, lane = tid & 31;
    if (lane == 0) { wS[warp] = accS; wC[warp] = accC; }
    __syncthreads();
    if (tid == 0) {
        float bs = 0.f, bc = 0.f;
        #pragma unroll
        for (int wi = 0; wi < OC / 32; wi++) { bs += wS[wi]; bc += wC[wi]; }
        atomicAdd(&g_acc[2 * level],     (double)bs);
        atomicAdd(&g_acc[2 * level + 1], (double)bc);
    }
}

// Fused 2x avg-pool of both images; float4 loads, float2 stores; shift math.
__global__ void pool2_kernel(const float* __restrict__ s1, const float* __restrict__ s2,
                             float* __restrict__ d1, float* __restrict__ d2,
                             int logWs, int total2) {
    int idx = blockIdx.x * blockDim.x + threadIdx.x;
    if (idx >= total2) return;
    const int whalf_bits = logWs - 2;
    const int ho_bits    = logWs - 1;
    int xp = idx & ((1 << whalf_bits) - 1);
    int t  = idx >> whalf_bits;
    int y  = t & ((1 << ho_bits) - 1);
    int z  = t >> ho_bits;
    size_t off = (((size_t)((z << logWs) + (y << 1))) << logWs) + ((size_t)xp << 2);
    int Ws = 1 << logWs;

    float4 a0 = *(const float4*)(s1 + off);
    float4 a1 = *(const float4*)(s1 + off + Ws);
    float4 b0 = *(const float4*)(s2 + off);
    float4 b1 = *(const float4*)(s2 + off + Ws);

    float2 oa = make_float2(0.25f * (a0.x + a0.y + a1.x + a1.y),
                            0.25f * (a0.z + a0.w + a1.z + a1.w));
    float2 ob = make_float2(0.25f * (b0.x + b0.y + b1.x + b1.y),
                            0.25f * (b0.z + b0.w + b1.z + b1.w));
    ((float2*)d1)[idx] = oa;
    ((float2*)d2)[idx] = ob;
}

__global__ void final_kernel(float* __restrict__ out) {
    const double Hl[5] = {502.0, 246.0, 118.0, 54.0, 22.0};
    const double Wt[5] = {0.0448, 0.2856, 0.3001, 0.2363, 0.1333};
    double prod = 1.0;
    double ms4 = 0.0;
    for (int l = 0; l < 5; l++) {
        double cnt = 48.0 * Hl[l] * Hl[l];
        double ms = (g_acc[2 * l]     / cnt + 1.0) * 0.5;
        double mc = (g_acc[2 * l + 1] / cnt + 1.0) * 0.5;
        if (l < 4) prod *= pow(mc, Wt[l]);
        else       ms4 = pow(ms, Wt[4]);
    }
    prod *= ms4 * ms4 * ms4 * ms4;   // pow2[-1] enters all 4 product terms
    out[0] = (float)prod;
}

static inline void launch_level(const float* a, const float* b, int H, int level) {
    int outw = H - 10;
    dim3 grid((outw + OC - 1) / OC, (outw + ORR - 1) / ORR, 48);
    ssim_level_kernel<<<grid, OC>>>(a, b, H, level);
}

static inline void launch_pool(const float* s1, const float* s2,
                               float* d1, float* d2, int logWs) {
    int Ws = 1 << logWs;
    int total2 = 48 * (Ws >> 1) * (Ws >> 2);
    pool2_kernel<<<(total2 + 255) / 256, 256>>>(s1, s2, d1, d2, logWs, total2);
}

extern "C" void kernel_launch(void* const* d_in, const int* in_sizes, int n_in,
                              void* d_out, int out_size) {
    const float* img1 = (const float*)d_in[0];
    const float* img2 = (const float*)d_in[1];
    float* out = (float*)d_out;

    float* p1; float* p2;
    cudaGetSymbolAddress((void**)&p1, g_p1);
    cudaGetSymbolAddress((void**)&p2, g_p2);

    zero_acc_kernel<<<1, 32>>>();

    launch_level(img1, img2, 512, 0);
    launch_pool(img1, img2, p1 + O1, p2 + O1, 9);

    launch_level(p1 + O1, p2 + O1, 256, 1);
    launch_pool(p1 + O1, p2 + O1, p1 + O2, p2 + O2, 8);

    launch_level(p1 + O2, p2 + O2, 128, 2);
    launch_pool(p1 + O2, p2 + O2, p1 + O3, p2 + O3, 7);

    launch_level(p1 + O3, p2 + O3, 64, 3);
    launch_pool(p1 + O3, p2 + O3, p1 + O4, p2 + O4, 6);

    launch_level(p1 + O4, p2 + O4, 32, 4);

    final_kernel<<<1, 1>>>(out);
}

// round 10
// speedup vs baseline: 1.5145x; 1.1688x over previous
#include <cuda_runtime.h>
#include <cuda_bf16.h>
#include <math.h>

// ===========================================================================
// MS-SSIM 16x3x512x512 fp32, 5 levels.
// ssim_all_kernel: ONE launch covering all 5 levels (4464 blocks, linear
//   block index decoded to level/tile/channel) to eliminate per-level wave
//   quantization tails. Inner loop identical to round 9:
//   SMEM tile packed (u,w) = (a+b, a-b);
//   conv(a*b) = (conv(u^2)-conv(w^2))/4, etc.
//   horizontal: 11x (LDS.64 + mul2 + 2x fma2); vertical: 11x (2x fma2).
// pool2_kernel: fused 2x avg-pool of both images, float4 loads (runs first).
// ===========================================================================

#define OC  128           // output columns per block (== threads)
#define ORR 30            // output rows per block
#define IR  (ORR + 10)    // 40 input rows
#define ICW (OC + 10)     // 138 input cols

// Gaussian taps, sigma=1.5, ws=11
#define G0 0.00102838f
#define G1 0.00759876f
#define G2 0.03600077f
#define G3 0.10936069f
#define G4 0.21300553f
#define G5 0.26601172f

#define C1V 1.0e-4f
#define C2V 9.0e-4f

// Scratch for pooled pyramids
#define S1 (48u * 256u * 256u)
#define S2 (48u * 128u * 128u)
#define S3 (48u * 64u  * 64u)
#define S4 (48u * 32u  * 32u)
#define O1 0u
#define O2 (S1)
#define O3 (S1 + S2)
#define O4 (S1 + S2 + S3)
#define TOT (S1 + S2 + S3 + S4)

// per-level block counts (H=512,256,128,64,32; ORR=30, OC=128, 48 channels)
#define NB0 3264   // 4 x 17 x 48
#define NB1 864    // 2 x  9 x 48
#define NB2 192    // 1 x  4 x 48
#define NB3 96     // 1 x  2 x 48
#define NB4 48     // 1 x  1 x 48
#define NBALL (NB0 + NB1 + NB2 + NB3 + NB4)   // 4464

__device__ float g_p1[TOT];
__device__ float g_p2[TOT];
__device__ double g_acc[10];

// ---- f32x2 packed helpers -------------------------------------------------
typedef unsigned long long ull;
__device__ __forceinline__ ull pk2(float lo, float hi) {
    ull r;
    asm("mov.b64 %0, {%1, %2};" : "=l"(r) : "f"(lo), "f"(hi));
    return r;
}
__device__ __forceinline__ void upk2(ull v, float& lo, float& hi) {
    asm("mov.b64 {%0, %1}, %2;" : "=f"(lo), "=f"(hi) : "l"(v));
}
__device__ __forceinline__ ull fma2(ull a, ull b, ull c) {
    ull d;
    asm("fma.rn.f32x2 %0, %1, %2, %3;" : "=l"(d) : "l"(a), "l"(b), "l"(c));
    return d;
}
__device__ __forceinline__ ull mul2(ull a, ull b) {
    ull d;
    asm("mul.rn.f32x2 %0, %1, %2;" : "=l"(d) : "l"(a), "l"(b));
    return d;
}

__global__ void zero_acc_kernel() {
    if (threadIdx.x < 10) g_acc[threadIdx.x] = 0.0;
}

__global__ void __launch_bounds__(OC, 5)
ssim_all_kernel(const float* __restrict__ img1, const float* __restrict__ img2) {
    __shared__ float2 sUW[IR * ICW];   // packed (a+b, a-b)

    // ---- decode linear block id -> (level, bx, by, z) ----
    int lid = blockIdx.x;
    int level, H, GX, GY;
    if (lid < NB0)                    { level = 0; H = 512; GX = 4; GY = 17; }
    else if ((lid -= NB0) < NB1)      { level = 1; H = 256; GX = 2; GY = 9;  }
    else if ((lid -= NB1) < NB2)      { level = 2; H = 128; GX = 1; GY = 4;  }
    else if ((lid -= NB2) < NB3)      { level = 3; H = 64;  GX = 1; GY = 2;  }
    else { lid -= NB3;                  level = 4; H = 32;  GX = 1; GY = 1;  }
    const int bx = lid % GX;
    const int t1 = lid / GX;
    const int by = t1 % GY;
    const int z  = t1 / GY;

    const float* baseA;
    const float* baseB;
    if (level == 0) { baseA = img1; baseB = img2; }
    else {
        unsigned off = (level == 1) ? O1 : (level == 2) ? O2
                     : (level == 3) ? O3 : O4;
        baseA = g_p1 + off;
        baseB = g_p2 + off;
    }

    const int tid = threadIdx.x;
    const int rowBase = by * ORR;
    const int colBase = bx * OC;
    const int W = H;
    const size_t zoff = (size_t)z * H * W;
    const float* __restrict__ Ap = baseA + zoff;
    const float* __restrict__ Bp = baseB + zoff;

    // ---- load tile as (u,w) (zero-clamped halo; masked outputs) ----
    for (int i = tid; i < IR * ICW; i += OC) {
        int r = i / ICW;
        int c = i - r * ICW;
        int gr = rowBase + r, gc = colBase + c;
        float u = 0.f, w = 0.f;
        if (gr < H && gc < W) {
            size_t o = (size_t)gr * W + gc;
            float a = __ldg(Ap + o);
            float b = __ldg(Bp + o);
            u = a + b;
            w = a - b;
        }
        sUW[i] = make_float2(u, w);
    }
    __syncthreads();

    const int oc = colBase + tid;
    const bool col_ok = oc < (W - 10);

    // 6 distinct packed taps (symmetry)
    ull Gp[6];
    Gp[0] = pk2(G0, G0); Gp[1] = pk2(G1, G1); Gp[2] = pk2(G2, G2);
    Gp[3] = pk2(G3, G3); Gp[4] = pk2(G4, G4); Gp[5] = pk2(G5, G5);

    // two packed register rings: conv(u,w) and conv(u^2,w^2)
    ull rUW[11], rSQ[11];
    float accS = 0.f, accC = 0.f;

    #pragma unroll
    for (int r = 0; r < IR; r++) {
        // ---- horizontal pass: 11x (LDS.64 + mul2 + 2x fma2) ----
        ull sUWa = 0ull, sSQa = 0ull;
        const ull* __restrict__ rowp =
            reinterpret_cast<const ull*>(&sUW[r * ICW]) + tid;
        #pragma unroll
        for (int k = 0; k < 11; k++) {
            ull vp = rowp[k];                         // LDS.64 (u,w)
            ull g  = Gp[k < 6 ? k : 10 - k];
            sUWa = fma2(vp, g, sUWa);
            sSQa = fma2(mul2(vp, vp), g, sSQa);
        }
        const int slot = r % 11;                      // compile-time
        rUW[slot] = sUWa;
        rSQ[slot] = sSQa;

        // ---- vertical pass: 11x (2x fma2) ----
        if (r >= 10) {
            ull mUW = 0ull, mSQ = 0ull;
            #pragma unroll
            for (int j = 0; j < 11; j++) {
                const int sl = (r - 10 + j) % 11;     // compile-time
                ull g = Gp[j < 6 ? j : 10 - j];
                mUW = fma2(rUW[sl], g, mUW);
                mSQ = fma2(rSQ[sl], g, mSQ);
            }
            int gr = rowBase + r;
            if (col_ok && gr < H) {
                float cU2, cW2, p, q;
                upk2(mSQ, cU2, cW2);
                ull pq = mul2(mUW, mUW);              // (cu^2, cw^2)
                upk2(pq, p, q);
                float n1 = 0.5f * (p - q) + C1V;
                float d1 = 0.5f * (p + q) + C1V;
                float v1 = 0.5f * ((cU2 - cW2) - (p - q)) + C2V;
                float v2 = 0.5f * ((cU2 + cW2) - (p + q)) + C2V;
                float cs = __fdividef(v1, v2);
                float ssim = cs * __fdividef(n1, d1);
                accS += ssim;
                accC += cs;
            }
        }
    }

    // ---- block reduction ----
    #pragma unroll
    for (int off = 16; off > 0; off >>= 1) {
        accS += __shfl_down_sync(0xFFFFFFFFu, accS, off);
        accC += __shfl_down_sync(0xFFFFFFFFu, accC, off);
    }
    __shared__ float wS[OC / 32], wC[OC / 32];
    const int warp = tid >> 5, lane = tid & 31;
    if (lane == 0) { wS[warp] = accS; wC[warp] = accC; }
    __syncthreads();
    if (tid == 0) {
        float bs = 0.f, bc = 0.f;
        #pragma unroll
        for (int wi = 0; wi < OC / 32; wi++) { bs += wS[wi]; bc += wC[wi]; }
        atomicAdd(&g_acc[2 * level],     (double)bs);
        atomicAdd(&g_acc[2 * level + 1], (double)bc);
    }
}

// Fused 2x avg-pool of both images; float4 loads, float2 stores; shift math.
__global__ void pool2_kernel(const float* __restrict__ s1, const float* __restrict__ s2,
                             float* __restrict__ d1, float* __restrict__ d2,
                             int logWs, int total2) {
    int idx = blockIdx.x * blockDim.x + threadIdx.x;
    if (idx >= total2) return;
    const int whalf_bits = logWs - 2;
    const int ho_bits    = logWs - 1;
    int xp = idx & ((1 << whalf_bits) - 1);
    int t  = idx >> whalf_bits;
    int y  = t & ((1 << ho_bits) - 1);
    int z  = t >> ho_bits;
    size_t off = (((size_t)((z << logWs) + (y << 1))) << logWs) + ((size_t)xp << 2);
    int Ws = 1 << logWs;

    float4 a0 = *(const float4*)(s1 + off);
    float4 a1 = *(const float4*)(s1 + off + Ws);
    float4 b0 = *(const float4*)(s2 + off);
    float4 b1 = *(const float4*)(s2 + off + Ws);

    float2 oa = make_float2(0.25f * (a0.x + a0.y + a1.x + a1.y),
                            0.25f * (a0.z + a0.w + a1.z + a1.w));
    float2 ob = make_float2(0.25f * (b0.x + b0.y + b1.x + b1.y),
                            0.25f * (b0.z + b0.w + b1.z + b1.w));
    ((float2*)d1)[idx] = oa;
    ((float2*)d2)[idx] = ob;
}

__global__ void final_kernel(float* __restrict__ out) {
    const double Hl[5] = {502.0, 246.0, 118.0, 54.0, 22.0};
    const double Wt[5] = {0.0448, 0.2856, 0.3001, 0.2363, 0.1333};
    double prod = 1.0;
    double ms4 = 0.0;
    for (int l = 0; l < 5; l++) {
        double cnt = 48.0 * Hl[l] * Hl[l];
        double ms = (g_acc[2 * l]     / cnt + 1.0) * 0.5;
        double mc = (g_acc[2 * l + 1] / cnt + 1.0) * 0.5;
        if (l < 4) prod *= pow(mc, Wt[l]);
        else       ms4 = pow(ms, Wt[4]);
    }
    prod *= ms4 * ms4 * ms4 * ms4;   // pow2[-1] enters all 4 product terms
    out[0] = (float)prod;
}

static inline void launch_pool(const float* s1, const float* s2,
                               float* d1, float* d2, int logWs) {
    int Ws = 1 << logWs;
    int total2 = 48 * (Ws >> 1) * (Ws >> 2);
    pool2_kernel<<<(total2 + 255) / 256, 256>>>(s1, s2, d1, d2, logWs, total2);
}

extern "C" void kernel_launch(void* const* d_in, const int* in_sizes, int n_in,
                              void* d_out, int out_size) {
    const float* img1 = (const float*)d_in[0];
    const float* img2 = (const float*)d_in[1];
    float* out = (float*)d_out;

    float* p1; float* p2;
    cudaGetSymbolAddress((void**)&p1, g_p1);
    cudaGetSymbolAddress((void**)&p2, g_p2);

    zero_acc_kernel<<<1, 32>>>();

    // Build the whole pyramid first (short serial chain), then one
    // wave-packed ssim launch over all 5 levels.
    launch_pool(img1, img2,   p1 + O1, p2 + O1, 9);
    launch_pool(p1 + O1, p2 + O1, p1 + O2, p2 + O2, 8);
    launch_pool(p1 + O2, p2 + O2, p1 + O3, p2 + O3, 7);
    launch_pool(p1 + O3, p2 + O3, p1 + O4, p2 + O4, 6);

    ssim_all_kernel<<<NBALL, OC>>>(img1, img2);

    final_kernel<<<1, 1>>>(out);
}

// round 11
// speedup vs baseline: 1.5905x; 1.0502x over previous
#include <cuda_runtime.h>
#include <cuda_bf16.h>
#include <math.h>

// ===========================================================================
// MS-SSIM 16x3x512x512 fp32, 5 levels.
// pool_all_kernel: ONE launch builds the whole 4-level pyramid; each block
//   pools a 32x32 source tile hierarchically in SMEM (both images).
// ssim_all_kernel: ONE launch covering all 5 levels (5520 blocks, linear
//   block index decoded to level/tile/channel). ORR=24 + launch_bounds(128,6)
//   -> 6 CTAs/SM (24 warps). Inner loop = round-9 sum/diff transform:
//   SMEM tile packed (u,w) = (a+b, a-b);
//   horizontal: 11x (LDS.64 + mul2 + 2x fma2); vertical: 11x (2x fma2).
// ===========================================================================

#define OC  128           // output columns per block (== threads)
#define ORR 24            // output rows per block
#define IR  (ORR + 10)    // 34 input rows
#define ICW (OC + 10)     // 138 input cols

// Gaussian taps, sigma=1.5, ws=11
#define G0 0.00102838f
#define G1 0.00759876f
#define G2 0.03600077f
#define G3 0.10936069f
#define G4 0.21300553f
#define G5 0.26601172f

#define C1V 1.0e-4f
#define C2V 9.0e-4f

// Scratch for pooled pyramids
#define S1 (48u * 256u * 256u)
#define S2 (48u * 128u * 128u)
#define S3 (48u * 64u  * 64u)
#define S4 (48u * 32u  * 32u)
#define O1 0u
#define O2 (S1)
#define O3 (S1 + S2)
#define O4 (S1 + S2 + S3)
#define TOT (S1 + S2 + S3 + S4)

// per-level block counts (ORR=24: GY = ceil((H-10)/24))
#define NB0 4032   // 4 x 21 x 48   (H=512)
#define NB1 1056   // 2 x 11 x 48   (H=256)
#define NB2 240    // 1 x  5 x 48   (H=128)
#define NB3 144    // 1 x  3 x 48   (H=64)
#define NB4 48     // 1 x  1 x 48   (H=32)
#define NBALL (NB0 + NB1 + NB2 + NB3 + NB4)   // 5520

__device__ float g_p1[TOT];
__device__ float g_p2[TOT];
__device__ double g_acc[10];

// ---- f32x2 packed helpers -------------------------------------------------
typedef unsigned long long ull;
__device__ __forceinline__ ull pk2(float lo, float hi) {
    ull r;
    asm("mov.b64 %0, {%1, %2};" : "=l"(r) : "f"(lo), "f"(hi));
    return r;
}
__device__ __forceinline__ void upk2(ull v, float& lo, float& hi) {
    asm("mov.b64 {%0, %1}, %2;" : "=f"(lo), "=f"(hi) : "l"(v));
}
__device__ __forceinline__ ull fma2(ull a, ull b, ull c) {
    ull d;
    asm("fma.rn.f32x2 %0, %1, %2, %3;" : "=l"(d) : "l"(a), "l"(b), "l"(c));
    return d;
}
__device__ __forceinline__ ull mul2(ull a, ull b) {
    ull d;
    asm("mul.rn.f32x2 %0, %1, %2;" : "=l"(d) : "l"(a), "l"(b));
    return d;
}

__global__ void zero_acc_kernel() {
    if (threadIdx.x < 10) g_acc[threadIdx.x] = 0.0;
}

// ---- one-shot pyramid builder ----------------------------------------------
// grid: 48*16*16 blocks of 256 threads; block handles one channel's 32x32
// source tile for BOTH images, producing L1..L4 hierarchically in SMEM.
__global__ void __launch_bounds__(256)
pool_all_kernel(const float* __restrict__ A, const float* __restrict__ B) {
    const int bid = blockIdx.x;
    const int tx = bid & 15;
    const int ty = (bid >> 4) & 15;
    const int z  = bid >> 8;

    __shared__ float hA[32][17], hB[32][17];
    __shared__ float l1A[16][17], l1B[16][17];
    __shared__ float l2A[8][9],  l2B[8][9];
    __shared__ float l3A[4][5],  l3B[4][5];

    const int t = threadIdx.x;

    // load 32x32 tile (each thread one float4 per image), horizontal pairs
    {
        const int r  = t >> 3;
        const int c4 = t & 7;
        size_t src = (((size_t)z * 512) + ty * 32 + r) * 512 + tx * 32 + c4 * 4;
        float4 a = *(const float4*)(A + src);
        float4 b = *(const float4*)(B + src);
        hA[r][c4 * 2]     = a.x + a.y;
        hA[r][c4 * 2 + 1] = a.z + a.w;
        hB[r][c4 * 2]     = b.x + b.y;
        hB[r][c4 * 2 + 1] = b.z + b.w;
    }
    __syncthreads();

    // L1: 16x16
    {
        const int y = t >> 4, x = t & 15;
        float va = 0.25f * (hA[2 * y][x] + hA[2 * y + 1][x]);
        float vb = 0.25f * (hB[2 * y][x] + hB[2 * y + 1][x]);
        l1A[y][x] = va; l1B[y][x] = vb;
        size_t o = (((size_t)z * 256) + ty * 16 + y) * 256 + tx * 16 + x;
        g_p1[O1 + o] = va;
        g_p2[O1 + o] = vb;
    }
    __syncthreads();

    // L2: 8x8
    if (t < 64) {
        const int y = t >> 3, x = t & 7;
        float va = 0.25f * (l1A[2*y][2*x] + l1A[2*y][2*x+1] +
                            l1A[2*y+1][2*x] + l1A[2*y+1][2*x+1]);
        float vb = 0.25f * (l1B[2*y][2*x] + l1B[2*y][2*x+1] +
                            l1B[2*y+1][2*x] + l1B[2*y+1][2*x+1]);
        l2A[y][x] = va; l2B[y][x] = vb;
        size_t o = (((size_t)z * 128) + ty * 8 + y) * 128 + tx * 8 + x;
        g_p1[O2 + o] = va;
        g_p2[O2 + o] = vb;
    }
    __syncthreads();

    // L3: 4x4
    if (t < 16) {
        const int y = t >> 2, x = t & 3;
        float va = 0.25f * (l2A[2*y][2*x] + l2A[2*y][2*x+1] +
                            l2A[2*y+1][2*x] + l2A[2*y+1][2*x+1]);
        float vb = 0.25f * (l2B[2*y][2*x] + l2B[2*y][2*x+1] +
                            l2B[2*y+1][2*x] + l2B[2*y+1][2*x+1]);
        l3A[y][x] = va; l3B[y][x] = vb;
        size_t o = (((size_t)z * 64) + ty * 4 + y) * 64 + tx * 4 + x;
        g_p1[O3 + o] = va;
        g_p2[O3 + o] = vb;
    }
    __syncthreads();

    // L4: 2x2
    if (t < 4) {
        const int y = t >> 1, x = t & 1;
        float va = 0.25f * (l3A[2*y][2*x] + l3A[2*y][2*x+1] +
                            l3A[2*y+1][2*x] + l3A[2*y+1][2*x+1]);
        float vb = 0.25f * (l3B[2*y][2*x] + l3B[2*y][2*x+1] +
                            l3B[2*y+1][2*x] + l3B[2*y+1][2*x+1]);
        size_t o = (((size_t)z * 32) + ty * 2 + y) * 32 + tx * 2 + x;
        g_p1[O4 + o] = va;
        g_p2[O4 + o] = vb;
    }
}

__global__ void __launch_bounds__(OC, 6)
ssim_all_kernel(const float* __restrict__ img1, const float* __restrict__ img2) {
    __shared__ float2 sUW[IR * ICW];   // packed (a+b, a-b)

    // ---- decode linear block id -> (level, bx, by, z) ----
    int lid = blockIdx.x;
    int level, H, GX, GY;
    if (lid < NB0)                    { level = 0; H = 512; GX = 4; GY = 21; }
    else if ((lid -= NB0) < NB1)      { level = 1; H = 256; GX = 2; GY = 11; }
    else if ((lid -= NB1) < NB2)      { level = 2; H = 128; GX = 1; GY = 5;  }
    else if ((lid -= NB2) < NB3)      { level = 3; H = 64;  GX = 1; GY = 3;  }
    else { lid -= NB3;                  level = 4; H = 32;  GX = 1; GY = 1;  }
    const int bx = lid % GX;
    const int t1 = lid / GX;
    const int by = t1 % GY;
    const int z  = t1 / GY;

    const float* baseA;
    const float* baseB;
    if (level == 0) { baseA = img1; baseB = img2; }
    else {
        unsigned off = (level == 1) ? O1 : (level == 2) ? O2
                     : (level == 3) ? O3 : O4;
        baseA = g_p1 + off;
        baseB = g_p2 + off;
    }

    const int tid = threadIdx.x;
    const int rowBase = by * ORR;
    const int colBase = bx * OC;
    const int W = H;
    const size_t zoff = (size_t)z * H * W;
    const float* __restrict__ Ap = baseA + zoff;
    const float* __restrict__ Bp = baseB + zoff;

    // ---- load tile as (u,w) (zero-clamped halo; masked outputs) ----
    for (int i = tid; i < IR * ICW; i += OC) {
        int r = i / ICW;
        int c = i - r * ICW;
        int gr = rowBase + r, gc = colBase + c;
        float u = 0.f, w = 0.f;
        if (gr < H && gc < W) {
            size_t o = (size_t)gr * W + gc;
            float a = __ldg(Ap + o);
            float b = __ldg(Bp + o);
            u = a + b;
            w = a - b;
        }
        sUW[i] = make_float2(u, w);
    }
    __syncthreads();

    const int oc = colBase + tid;
    const bool col_ok = oc < (W - 10);

    // 6 distinct packed taps (symmetry)
    ull Gp[6];
    Gp[0] = pk2(G0, G0); Gp[1] = pk2(G1, G1); Gp[2] = pk2(G2, G2);
    Gp[3] = pk2(G3, G3); Gp[4] = pk2(G4, G4); Gp[5] = pk2(G5, G5);

    // two packed register rings: conv(u,w) and conv(u^2,w^2)
    ull rUW[11], rSQ[11];
    float accS = 0.f, accC = 0.f;

    #pragma unroll
    for (int r = 0; r < IR; r++) {
        // ---- horizontal pass: 11x (LDS.64 + mul2 + 2x fma2) ----
        ull sUWa = 0ull, sSQa = 0ull;
        const ull* __restrict__ rowp =
            reinterpret_cast<const ull*>(&sUW[r * ICW]) + tid;
        #pragma unroll
        for (int k = 0; k < 11; k++) {
            ull vp = rowp[k];                         // LDS.64 (u,w)
            ull g  = Gp[k < 6 ? k : 10 - k];
            sUWa = fma2(vp, g, sUWa);
            sSQa = fma2(mul2(vp, vp), g, sSQa);
        }
        const int slot = r % 11;                      // compile-time
        rUW[slot] = sUWa;
        rSQ[slot] = sSQa;

        // ---- vertical pass: 11x (2x fma2) ----
        if (r >= 10) {
            ull mUW = 0ull, mSQ = 0ull;
            #pragma unroll
            for (int j = 0; j < 11; j++) {
                const int sl = (r - 10 + j) % 11;     // compile-time
                ull g = Gp[j < 6 ? j : 10 - j];
                mUW = fma2(rUW[sl], g, mUW);
                mSQ = fma2(rSQ[sl], g, mSQ);
            }
            int gr = rowBase + r;
            if (col_ok && gr < H) {
                float cU2, cW2, p, q;
                upk2(mSQ, cU2, cW2);
                ull pq = mul2(mUW, mUW);              // (cu^2, cw^2)
                upk2(pq, p, q);
                float n1 = 0.5f * (p - q) + C1V;
                float d1 = 0.5f * (p + q) + C1V;
                float v1 = 0.5f * ((cU2 - cW2) - (p - q)) + C2V;
                float v2 = 0.5f * ((cU2 + cW2) - (p + q)) + C2V;
                float cs = __fdividef(v1, v2);
                float ssim = cs * __fdividef(n1, d1);
                accS += ssim;
                accC += cs;
            }
        }
    }

    // ---- block reduction ----
    #pragma unroll
    for (int off = 16; off > 0; off >>= 1) {
        accS += __shfl_down_sync(0xFFFFFFFFu, accS, off);
        accC += __shfl_down_sync(0xFFFFFFFFu, accC, off);
    }
    __shared__ float wS[OC / 32], wC[OC / 32];
    const int warp = tid >> 5, lane = tid & 31;
    if (lane == 0) { wS[warp] = accS; wC[warp] = accC; }
    __syncthreads();
    if (tid == 0) {
        float bs = 0.f, bc = 0.f;
        #pragma unroll
        for (int wi = 0; wi < OC / 32; wi++) { bs += wS[wi]; bc += wC[wi]; }
        atomicAdd(&g_acc[2 * level],     (double)bs);
        atomicAdd(&g_acc[2 * level + 1], (double)bc);
    }
}

__global__ void final_kernel(float* __restrict__ out) {
    const double Hl[5] = {502.0, 246.0, 118.0, 54.0, 22.0};
    const double Wt[5] = {0.0448, 0.2856, 0.3001, 0.2363, 0.1333};
    double prod = 1.0;
    double ms4 = 0.0;
    for (int l = 0; l < 5; l++) {
        double cnt = 48.0 * Hl[l] * Hl[l];
        double ms = (g_acc[2 * l]     / cnt + 1.0) * 0.5;
        double mc = (g_acc[2 * l + 1] / cnt + 1.0) * 0.5;
        if (l < 4) prod *= pow(mc, Wt[l]);
        else       ms4 = pow(ms, Wt[4]);
    }
    prod *= ms4 * ms4 * ms4 * ms4;   // pow2[-1] enters all 4 product terms
    out[0] = (float)prod;
}

extern "C" void kernel_launch(void* const* d_in, const int* in_sizes, int n_in,
                              void* d_out, int out_size) {
    const float* img1 = (const float*)d_in[0];
    const float* img2 = (const float*)d_in[1];
    float* out = (float*)d_out;

    zero_acc_kernel<<<1, 32>>>();

    // one launch builds the whole pyramid, then one wave-packed ssim launch
    pool_all_kernel<<<48 * 16 * 16, 256>>>(img1, img2);

    ssim_all_kernel<<<NBALL, OC>>>(img1, img2);

    final_kernel<<<1, 1>>>(out);
}

// round 12
// speedup vs baseline: 1.7740x; 1.1154x over previous
#include <cuda_runtime.h>
#include <cuda_bf16.h>
#include <math.h>

// ===========================================================================
// MS-SSIM 16x3x512x512 fp32, 5 levels.
// pool_all_kernel: ONE launch builds the whole 4-level pyramid; each block
//   pools a 32x32 source tile hierarchically in SMEM (both images).
//   Block 0 also zeroes the g_acc accumulators (replaces zero_acc launch).
// ssim_all_kernel: ONE launch covering all 5 levels (5520 blocks), 6 CTAs/SM.
//   Inner loop = sum/diff transform, packed f32x2 FMA.
// final_kernel: fp32 log2/exp2 combine (was 20us of double pow -> ~2us).
// ===========================================================================

#define OC  128           // output columns per block (== threads)
#define ORR 24            // output rows per block
#define IR  (ORR + 10)    // 34 input rows
#define ICW (OC + 10)     // 138 input cols

// Gaussian taps, sigma=1.5, ws=11
#define G0 0.00102838f
#define G1 0.00759876f
#define G2 0.03600077f
#define G3 0.10936069f
#define G4 0.21300553f
#define G5 0.26601172f

#define C1V 1.0e-4f
#define C2V 9.0e-4f

// Scratch for pooled pyramids
#define S1 (48u * 256u * 256u)
#define S2 (48u * 128u * 128u)
#define S3 (48u * 64u  * 64u)
#define S4 (48u * 32u  * 32u)
#define O1 0u
#define O2 (S1)
#define O3 (S1 + S2)
#define O4 (S1 + S2 + S3)
#define TOT (S1 + S2 + S3 + S4)

// per-level block counts (ORR=24: GY = ceil((H-10)/24))
#define NB0 4032   // 4 x 21 x 48   (H=512)
#define NB1 1056   // 2 x 11 x 48   (H=256)
#define NB2 240    // 1 x  5 x 48   (H=128)
#define NB3 144    // 1 x  3 x 48   (H=64)
#define NB4 48     // 1 x  1 x 48   (H=32)
#define NBALL (NB0 + NB1 + NB2 + NB3 + NB4)   // 5520

__device__ float g_p1[TOT];
__device__ float g_p2[TOT];
__device__ double g_acc[10];

// ---- f32x2 packed helpers -------------------------------------------------
typedef unsigned long long ull;
__device__ __forceinline__ ull pk2(float lo, float hi) {
    ull r;
    asm("mov.b64 %0, {%1, %2};" : "=l"(r) : "f"(lo), "f"(hi));
    return r;
}
__device__ __forceinline__ void upk2(ull v, float& lo, float& hi) {
    asm("mov.b64 {%0, %1}, %2;" : "=f"(lo), "=f"(hi) : "l"(v));
}
__device__ __forceinline__ ull fma2(ull a, ull b, ull c) {
    ull d;
    asm("fma.rn.f32x2 %0, %1, %2, %3;" : "=l"(d) : "l"(a), "l"(b), "l"(c));
    return d;
}
__device__ __forceinline__ ull mul2(ull a, ull b) {
    ull d;
    asm("mul.rn.f32x2 %0, %1, %2;" : "=l"(d) : "l"(a), "l"(b));
    return d;
}

// ---- one-shot pyramid builder ----------------------------------------------
// grid: 48*16*16 blocks of 256 threads; block handles one channel's 32x32
// source tile for BOTH images, producing L1..L4 hierarchically in SMEM.
__global__ void __launch_bounds__(256)
pool_all_kernel(const float* __restrict__ A, const float* __restrict__ B) {
    const int bid = blockIdx.x;
    const int tx = bid & 15;
    const int ty = (bid >> 4) & 15;
    const int z  = bid >> 8;

    __shared__ float hA[32][17], hB[32][17];
    __shared__ float l1A[16][17], l1B[16][17];
    __shared__ float l2A[8][9],  l2B[8][9];
    __shared__ float l3A[4][5],  l3B[4][5];

    const int t = threadIdx.x;

    // block 0 zeroes the level accumulators (pool_all precedes ssim_all)
    if (bid == 0 && t < 10) g_acc[t] = 0.0;

    // load 32x32 tile (each thread one float4 per image), horizontal pairs
    {
        const int r  = t >> 3;
        const int c4 = t & 7;
        size_t src = (((size_t)z * 512) + ty * 32 + r) * 512 + tx * 32 + c4 * 4;
        float4 a = *(const float4*)(A + src);
        float4 b = *(const float4*)(B + src);
        hA[r][c4 * 2]     = a.x + a.y;
        hA[r][c4 * 2 + 1] = a.z + a.w;
        hB[r][c4 * 2]     = b.x + b.y;
        hB[r][c4 * 2 + 1] = b.z + b.w;
    }
    __syncthreads();

    // L1: 16x16
    {
        const int y = t >> 4, x = t & 15;
        float va = 0.25f * (hA[2 * y][x] + hA[2 * y + 1][x]);
        float vb = 0.25f * (hB[2 * y][x] + hB[2 * y + 1][x]);
        l1A[y][x] = va; l1B[y][x] = vb;
        size_t o = (((size_t)z * 256) + ty * 16 + y) * 256 + tx * 16 + x;
        g_p1[O1 + o] = va;
        g_p2[O1 + o] = vb;
    }
    __syncthreads();

    // L2: 8x8
    if (t < 64) {
        const int y = t >> 3, x = t & 7;
        float va = 0.25f * (l1A[2*y][2*x] + l1A[2*y][2*x+1] +
                            l1A[2*y+1][2*x] + l1A[2*y+1][2*x+1]);
        float vb = 0.25f * (l1B[2*y][2*x] + l1B[2*y][2*x+1] +
                            l1B[2*y+1][2*x] + l1B[2*y+1][2*x+1]);
        l2A[y][x] = va; l2B[y][x] = vb;
        size_t o = (((size_t)z * 128) + ty * 8 + y) * 128 + tx * 8 + x;
        g_p1[O2 + o] = va;
        g_p2[O2 + o] = vb;
    }
    __syncthreads();

    // L3: 4x4
    if (t < 16) {
        const int y = t >> 2, x = t & 3;
        float va = 0.25f * (l2A[2*y][2*x] + l2A[2*y][2*x+1] +
                            l2A[2*y+1][2*x] + l2A[2*y+1][2*x+1]);
        float vb = 0.25f * (l2B[2*y][2*x] + l2B[2*y][2*x+1] +
                            l2B[2*y+1][2*x] + l2B[2*y+1][2*x+1]);
        l3A[y][x] = va; l3B[y][x] = vb;
        size_t o = (((size_t)z * 64) + ty * 4 + y) * 64 + tx * 4 + x;
        g_p1[O3 + o] = va;
        g_p2[O3 + o] = vb;
    }
    __syncthreads();

    // L4: 2x2
    if (t < 4) {
        const int y = t >> 1, x = t & 1;
        float va = 0.25f * (l3A[2*y][2*x] + l3A[2*y][2*x+1] +
                            l3A[2*y+1][2*x] + l3A[2*y+1][2*x+1]);
        float vb = 0.25f * (l3B[2*y][2*x] + l3B[2*y][2*x+1] +
                            l3B[2*y+1][2*x] + l3B[2*y+1][2*x+1]);
        size_t o = (((size_t)z * 32) + ty * 2 + y) * 32 + tx * 2 + x;
        g_p1[O4 + o] = va;
        g_p2[O4 + o] = vb;
    }
}

__global__ void __launch_bounds__(OC, 6)
ssim_all_kernel(const float* __restrict__ img1, const float* __restrict__ img2) {
    __shared__ float2 sUW[IR * ICW];   // packed (a+b, a-b)

    // ---- decode linear block id -> (level, bx, by, z) ----
    int lid = blockIdx.x;
    int level, H, GX, GY;
    if (lid < NB0)                    { level = 0; H = 512; GX = 4; GY = 21; }
    else if ((lid -= NB0) < NB1)      { level = 1; H = 256; GX = 2; GY = 11; }
    else if ((lid -= NB1) < NB2)      { level = 2; H = 128; GX = 1; GY = 5;  }
    else if ((lid -= NB2) < NB3)      { level = 3; H = 64;  GX = 1; GY = 3;  }
    else { lid -= NB3;                  level = 4; H = 32;  GX = 1; GY = 1;  }
    const int bx = lid % GX;
    const int t1 = lid / GX;
    const int by = t1 % GY;
    const int z  = t1 / GY;

    const float* baseA;
    const float* baseB;
    if (level == 0) { baseA = img1; baseB = img2; }
    else {
        unsigned off = (level == 1) ? O1 : (level == 2) ? O2
                     : (level == 3) ? O3 : O4;
        baseA = g_p1 + off;
        baseB = g_p2 + off;
    }

    const int tid = threadIdx.x;
    const int rowBase = by * ORR;
    const int colBase = bx * OC;
    const int W = H;
    const size_t zoff = (size_t)z * H * W;
    const float* __restrict__ Ap = baseA + zoff;
    const float* __restrict__ Bp = baseB + zoff;

    // ---- load tile as (u,w) (zero-clamped halo; masked outputs) ----
    for (int i = tid; i < IR * ICW; i += OC) {
        int r = i / ICW;
        int c = i - r * ICW;
        int gr = rowBase + r, gc = colBase + c;
        float u = 0.f, w = 0.f;
        if (gr < H && gc < W) {
            size_t o = (size_t)gr * W + gc;
            float a = __ldg(Ap + o);
            float b = __ldg(Bp + o);
            u = a + b;
            w = a - b;
        }
        sUW[i] = make_float2(u, w);
    }
    __syncthreads();

    const int oc = colBase + tid;
    const bool col_ok = oc < (W - 10);

    // 6 distinct packed taps (symmetry)
    ull Gp[6];
    Gp[0] = pk2(G0, G0); Gp[1] = pk2(G1, G1); Gp[2] = pk2(G2, G2);
    Gp[3] = pk2(G3, G3); Gp[4] = pk2(G4, G4); Gp[5] = pk2(G5, G5);

    // two packed register rings: conv(u,w) and conv(u^2,w^2)
    ull rUW[11], rSQ[11];
    float accS = 0.f, accC = 0.f;

    #pragma unroll
    for (int r = 0; r < IR; r++) {
        // ---- horizontal pass: 11x (LDS.64 + mul2 + 2x fma2) ----
        ull sUWa = 0ull, sSQa = 0ull;
        const ull* __restrict__ rowp =
            reinterpret_cast<const ull*>(&sUW[r * ICW]) + tid;
        #pragma unroll
        for (int k = 0; k < 11; k++) {
            ull vp = rowp[k];                         // LDS.64 (u,w)
            ull g  = Gp[k < 6 ? k : 10 - k];
            sUWa = fma2(vp, g, sUWa);
            sSQa = fma2(mul2(vp, vp), g, sSQa);
        }
        const int slot = r % 11;                      // compile-time
        rUW[slot] = sUWa;
        rSQ[slot] = sSQa;

        // ---- vertical pass: 11x (2x fma2) ----
        if (r >= 10) {
            ull mUW = 0ull, mSQ = 0ull;
            #pragma unroll
            for (int j = 0; j < 11; j++) {
                const int sl = (r - 10 + j) % 11;     // compile-time
                ull g = Gp[j < 6 ? j : 10 - j];
                mUW = fma2(rUW[sl], g, mUW);
                mSQ = fma2(rSQ[sl], g, mSQ);
            }
            int gr = rowBase + r;
            if (col_ok && gr < H) {
                float cU2, cW2, p, q;
                upk2(mSQ, cU2, cW2);
                ull pq = mul2(mUW, mUW);              // (cu^2, cw^2)
                upk2(pq, p, q);
                float n1 = 0.5f * (p - q) + C1V;
                float d1 = 0.5f * (p + q) + C1V;
                float v1 = 0.5f * ((cU2 - cW2) - (p - q)) + C2V;
                float v2 = 0.5f * ((cU2 + cW2) - (p + q)) + C2V;
                float cs = __fdividef(v1, v2);
                float ssim = cs * __fdividef(n1, d1);
                accS += ssim;
                accC += cs;
            }
        }
    }

    // ---- block reduction ----
    #pragma unroll
    for (int off = 16; off > 0; off >>= 1) {
        accS += __shfl_down_sync(0xFFFFFFFFu, accS, off);
        accC += __shfl_down_sync(0xFFFFFFFFu, accC, off);
    }
    __shared__ float wS[OC / 32], wC[OC / 32];
    const int warp = tid >> 5, lane = tid & 31;
    if (lane == 0) { wS[warp] = accS; wC[warp] = accC; }
    __syncthreads();
    if (tid == 0) {
        float bs = 0.f, bc = 0.f;
        #pragma unroll
        for (int wi = 0; wi < OC / 32; wi++) { bs += wS[wi]; bc += wC[wi]; }
        atomicAdd(&g_acc[2 * level],     (double)bs);
        atomicAdd(&g_acc[2 * level + 1], (double)bc);
    }
}

// fp32 combine via log2/exp2 (values in (0.9, 1.0]; rel. err ~1e-7 << 1e-3)
__global__ void final_kernel(float* __restrict__ out) {
    const float Hl[5] = {502.f, 246.f, 118.f, 54.f, 22.f};
    const float Wt[5] = {0.0448f, 0.2856f, 0.3001f, 0.2363f, 0.1333f};
    float lsum = 0.f;
    #pragma unroll
    for (int l = 0; l < 5; l++) {
        float inv_cnt = 1.f / (48.f * Hl[l] * Hl[l]);
        float ms = ((float)g_acc[2 * l]     * inv_cnt + 1.f) * 0.5f;
        float mc = ((float)g_acc[2 * l + 1] * inv_cnt + 1.f) * 0.5f;
        // prod(pow1[:-1] * pow2[-1]): mcs^{w_l} for l<4, mssim4^{4*w_4}
        float x = (l < 4) ? mc : ms;
        float w = (l < 4) ? Wt[l] : 4.f * Wt[4];
        lsum += w * log2f(x);
    }
    out[0] = exp2f(lsum);
}

extern "C" void kernel_launch(void* const* d_in, const int* in_sizes, int n_in,
                              void* d_out, int out_size) {
    const float* img1 = (const float*)d_in[0];
    const float* img2 = (const float*)d_in[1];
    float* out = (float*)d_out;

    // one launch builds the whole pyramid (and zeroes accumulators),
    // then one wave-packed ssim launch, then a tiny fp32 combine.
    pool_all_kernel<<<48 * 16 * 16, 256>>>(img1, img2);

    ssim_all_kernel<<<NBALL, OC>>>(img1, img2);

    final_kernel<<<1, 1>>>(out);
}